// round 14
// baseline (speedup 1.0000x reference)
#include <cuda_runtime.h>
#include <cuda_bf16.h>

#define Dm 1024
#define Tm 2048
#define Lm 4

typedef unsigned long long u64;

// ---------------- device scratch (allocation-free rule) ---------------------
__device__ __align__(16) float g_seq[2][Tm * Dm];              // ping-pong seq
__device__ __align__(16) float g_zx[(size_t)Tm * 4 * Dm];      // x-part + bias
__device__ __align__(16) float g_wt[(size_t)Lm * 4 * Dm * Dm]; // Wh^T [l][gate][dim][k]
__device__ __align__(16) float g_h[2][Dm];                     // h double buffer
__device__ __align__(16) unsigned g_tag[128];                  // per-CTA step tags

// ---------------- f32x2 helpers (sm_103a packed fp32) -----------------------
__device__ __forceinline__ u64 ffma2(u64 a, u64 b, u64 c) {
    u64 d;
    asm("fma.rn.f32x2 %0, %1, %2, %3;" : "=l"(d) : "l"(a), "l"(b), "l"(c));
    return d;
}
__device__ __forceinline__ u64 fadd2(u64 a, u64 b) {
    u64 d;
    asm("add.rn.f32x2 %0, %1, %2;" : "=l"(d) : "l"(a), "l"(b));
    return d;
}
__device__ __forceinline__ u64 pack2(float x, float y) {
    u64 r;
    asm("mov.b64 %0, {%1, %2};" : "=l"(r)
        : "r"(__float_as_uint(x)), "r"(__float_as_uint(y)));
    return r;
}
__device__ __forceinline__ float hsum2(u64 v) {
    unsigned lo, hi;
    asm("mov.b64 {%0, %1}, %2;" : "=r"(lo), "=r"(hi) : "l"(v));
    return __uint_as_float(lo) + __uint_as_float(hi);
}

// fast, saturation-safe tanh / sigmoid (MUFU-based)
__device__ __forceinline__ float fast_tanh(float x) {
    float e = __expf(-2.0f * fabsf(x));
    float r = __fdividef(1.0f - e, 1.0f + e);
    return copysignf(r, x);
}
__device__ __forceinline__ float fast_sigmoid(float u) {
    float e = __expf(-fabsf(u));
    float r = __fdividef(1.0f, 1.0f + e);
    return (u >= 0.0f) ? r : (1.0f - r);
}

// ---------------- kernel 1: Re bias-add + tag reset --------------------------
__global__ void bias_kernel(const float* __restrict__ x, const float* __restrict__ rn,
                            const float* __restrict__ w, const float* __restrict__ b) {
    if (blockIdx.x == 0 && threadIdx.x < 128) g_tag[threadIdx.x] = 0u;
    int i = blockIdx.x * 256 + threadIdx.x;
    int j = i & (Dm - 1);
    g_seq[0][i] = x[i] + rn[0] * w[j] + b[j];
}

// ---------------- kernel 1b: transpose Wh -> g_wt[l][gate][dim][k] ----------
__global__ void wt_kernel(const float* __restrict__ Wf1, const float* __restrict__ Wf2,
                          const float* __restrict__ Wta, const float* __restrict__ Wtb) {
    __shared__ float tile[32][33];
    const int lg = blockIdx.z;              // l*4 + gate
    const int l = lg >> 2, gate = lg & 3;
    const float* Wg = (gate == 0) ? Wf1 : ((gate == 1) ? Wf2 : ((gate == 2) ? Wta : Wtb));
    const float* W = Wg + (size_t)l * 2 * Dm * Dm;
    const int k0 = blockIdx.x * 32, d0 = blockIdx.y * 32;
    const int tx = threadIdx.x, ty = threadIdx.y;
#pragma unroll
    for (int r = ty; r < 32; r += 8)
        tile[r][tx] = W[(size_t)(Dm + k0 + r) * Dm + d0 + tx];   // h-part rows
    __syncthreads();
#pragma unroll
    for (int r = ty; r < 32; r += 8)
        g_wt[((size_t)lg * Dm + d0 + r) * Dm + k0 + tx] = tile[tx][r];
}

// ---------------- kernel 2: Zx = seq_in @ Wx + bias (f32x2 GEMM) -------------
__global__ __launch_bounds__(256, 2) void gemm_zx(
    const float* __restrict__ Wf1, const float* __restrict__ Wf2,
    const float* __restrict__ Wta, const float* __restrict__ Wtb,
    const float* __restrict__ bf1, const float* __restrict__ bf2,
    const float* __restrict__ bta, const float* __restrict__ btb,
    int layer)
{
    __shared__ u64   As2[8][128];
    __shared__ float Bsf[8][64][2];

    const int tid = threadIdx.x;
    const int tx = tid & 15;
    const int ty = tid >> 4;
    const int m0 = blockIdx.y * 128;
    const int n0 = blockIdx.x * 64;
    const int blk = n0 >> 10;
    const int j0  = n0 & (Dm - 1);

    const float* Wb = (blk == 0) ? Wf1 : ((blk == 1) ? Wf2 : ((blk == 2) ? Wta : Wtb));
    const float* bb = (blk == 0) ? bf1 : ((blk == 1) ? bf2 : ((blk == 2) ? bta : btb));
    const float* Bp = Wb + (size_t)layer * 2 * Dm * Dm + j0;
    const float* A  = g_seq[layer & 1];

    u64 acc[8][4];
#pragma unroll
    for (int i = 0; i < 8; i++)
#pragma unroll
        for (int j = 0; j < 4; j++) acc[i][j] = 0ull;

    for (int k0 = 0; k0 < Dm; k0 += 16) {
#pragma unroll
        for (int it = 0; it < 2; it++) {
            int i   = tid + it * 256;
            int row = i >> 2;
            int f4  = i & 3;
            float4 v = *(const float4*)(A + (size_t)(m0 + row) * Dm + k0 + f4 * 4);
            As2[f4 * 2 + 0][row] = pack2(v.x, v.y);
            As2[f4 * 2 + 1][row] = pack2(v.z, v.w);
        }
        {
            int kr = tid >> 4;
            int j4 = tid & 15;
            float4 v = *(const float4*)(Bp + (size_t)(k0 + kr) * Dm + j4 * 4);
            Bsf[kr >> 1][j4 * 4 + 0][kr & 1] = v.x;
            Bsf[kr >> 1][j4 * 4 + 1][kr & 1] = v.y;
            Bsf[kr >> 1][j4 * 4 + 2][kr & 1] = v.z;
            Bsf[kr >> 1][j4 * 4 + 3][kr & 1] = v.w;
        }
        __syncthreads();
#pragma unroll
        for (int kk = 0; kk < 8; kk++) {
            u64 a2[8], b2[4];
#pragma unroll
            for (int ii = 0; ii < 8; ii++) a2[ii] = As2[kk][ii * 16 + ty];
#pragma unroll
            for (int jj = 0; jj < 4; jj++) b2[jj] = *(const u64*)&Bsf[kk][jj * 16 + tx][0];
#pragma unroll
            for (int ii = 0; ii < 8; ii++)
#pragma unroll
                for (int jj = 0; jj < 4; jj++)
                    acc[ii][jj] = ffma2(a2[ii], b2[jj], acc[ii][jj]);
        }
        __syncthreads();
    }

    float bias[4];
#pragma unroll
    for (int jj = 0; jj < 4; jj++) bias[jj] = bb[(size_t)layer * Dm + j0 + jj * 16 + tx];
#pragma unroll
    for (int ii = 0; ii < 8; ii++) {
        size_t row = (size_t)(m0 + ii * 16 + ty);
#pragma unroll
        for (int jj = 0; jj < 4; jj++)
            g_zx[row * 4096 + n0 + jj * 16 + tx] = hsum2(acc[ii][jj]) + bias[jj];
    }
}

// ---------------- kernel 3: sequential scan (tag-array barrier) --------------
// 128 CTAs x 256 threads. CTA b owns dims 8b..8b+7, warp w -> dim.
// Producer: 8 lane0s st.relaxed h; smem atom counts warps; 8th warp does one
// st.release g_tag[b] = tagbase+t+1. Consumer: warp0 polls all 128 tags
// (v4 loads, 512B/sweep/CTA), fence.acq_rel, then all warps stage h via ldcg.
// Non-poll warps wait at __syncthreads (no LSU spin). Two BARs per step.
__global__ __launch_bounds__(256, 1) void scan_kernel(const float* __restrict__ dt_ptr,
                                                      int layer)
{
    __shared__ __align__(16) float sh[2][Dm];
    __shared__ unsigned s_acnt;

    const int tid  = threadIdx.x;
    const int lane = tid & 31;
    const int w    = tid >> 5;
    const int blk  = lane >> 3;
    const int ch   = lane & 7;
    const int dim  = blockIdx.x * 8 + w;
    const float dt = dt_ptr[0];
    const unsigned tagbase = (unsigned)layer * (unsigned)Tm;

    const unsigned acnt_a = (unsigned)__cvta_generic_to_shared(&s_acnt);
    if (tid == 0) s_acnt = 0u;

    // coalesced weight load from transposed scratch: [l][gate][dim][k]
    const float* Wtp = g_wt + ((size_t)(layer * 4 + blk) * Dm + dim) * Dm + ch * 128;
    u64 wreg[64];
#pragma unroll
    for (int i = 0; i < 32; i++) {
        float4 v = *(const float4*)(Wtp + 4 * i);
        wreg[2 * i + 0] = pack2(v.x, v.y);
        wreg[2 * i + 1] = pack2(v.z, v.w);
    }

    float* __restrict__ outseq = g_seq[(layer + 1) & 1];
    const bool zlane = (ch == 0);
    float zx_cur = zlane ? __ldg(&g_zx[(size_t)blk * Dm + dim]) : 0.0f;
    float h_keep = 0.0f;   // outseq stash: step (t & ~31) + lane

    const int sc = tid & 7, sf = tid >> 3;
    const float* const myh0 = &g_h[0][sc * 128 + sf * 4];
    const float* const myh1 = &g_h[1][sc * 128 + sf * 4];
    float* const mysh0 = &sh[0][sf * 32 + sc * 4];
    float* const mysh1 = &sh[1][sf * 32 + sc * 4];

    const unsigned* const mytags = &g_tag[lane * 4];

    __syncthreads();   // covers s_acnt init

    for (int t = 0; t < Tm; ++t) {
        // ---- acquire: warp0 polls all 128 per-CTA tags ----
        if (t > 0) {
            if (w == 0) {
                const unsigned target = tagbase + (unsigned)t;
                for (;;) {
                    unsigned a, b, c, d;
                    asm volatile("ld.volatile.global.v4.u32 {%0,%1,%2,%3}, [%4];"
                                 : "=r"(a), "=r"(b), "=r"(c), "=r"(d)
                                 : "l"(mytags) : "memory");
                    bool ok = (a >= target) && (b >= target) &&
                              (c >= target) && (d >= target);
                    if (__all_sync(0xffffffffu, ok)) break;
                }
                asm volatile("fence.acq_rel.gpu;" ::: "memory");
            }
            __syncthreads();   // BAR#1: release all warps after detection
        }

        // ---- stage h_t into smem (chunk-interleaved) ----
        float* mysh = (t & 1) ? mysh1 : mysh0;
        if (t == 0) {
            mysh[0] = 0.0f; mysh[1] = 0.0f; mysh[2] = 0.0f; mysh[3] = 0.0f;
        } else {
            float4 v = __ldcg((const float4*)((t & 1) ? myh1 : myh0));
            mysh[0] = v.x; mysh[1] = v.y; mysh[2] = v.z; mysh[3] = v.w;
        }
        __syncthreads();       // BAR#2: sh ready

        // zx prefetch for t+1 (independent; hides under compute)
        float zx_next = (zlane && t + 1 < Tm)
            ? __ldg(&g_zx[(size_t)(t + 1) * 4096 + blk * Dm + dim]) : 0.0f;

        // ---- partial dot: 128 k via 64 packed FMAs ----
        u64 a0 = 0ull, a1 = 0ull, a2 = 0ull, a3 = 0ull;
        const float4* sh4 = (const float4*)sh[t & 1];
#pragma unroll
        for (int f = 0; f < 32; f += 2) {
            float4 h0 = sh4[f * 8 + ch];
            float4 h1 = sh4[(f + 1) * 8 + ch];
            a0 = ffma2(pack2(h0.x, h0.y), wreg[2 * f + 0], a0);
            a1 = ffma2(pack2(h0.z, h0.w), wreg[2 * f + 1], a1);
            a2 = ffma2(pack2(h1.x, h1.y), wreg[2 * f + 2], a2);
            a3 = ffma2(pack2(h1.z, h1.w), wreg[2 * f + 3], a3);
        }
        float s = hsum2(fadd2(fadd2(a0, a1), fadd2(a2, a3)));
        s += __shfl_xor_sync(0xffffffffu, s, 1);
        s += __shfl_xor_sync(0xffffffffu, s, 2);
        s += __shfl_xor_sync(0xffffffffu, s, 4);
        if (zlane) s += zx_cur;

        float z1 = __shfl_sync(0xffffffffu, s, 0);
        float z2 = __shfl_sync(0xffffffffu, s, 8);
        float za = __shfl_sync(0xffffffffu, s, 16);
        float zb = __shfl_sync(0xffffffffu, s, 24);

        float f1 = fast_tanh(z1);
        float f2 = fast_tanh(z2);
        float g  = fast_sigmoid(zb - za * dt);
        float hn = g * f1 + (1.0f - g) * f2;

        // ---- publish h(t+1): relaxed store + smem-aggregated tag release ----
        if (lane == 0 && t + 1 < Tm) {
            asm volatile("st.relaxed.gpu.global.f32 [%0], %1;"
                         :: "l"(&g_h[(t + 1) & 1][dim]), "f"(hn) : "memory");
            unsigned old;
            asm volatile("atom.acq_rel.cta.shared.add.u32 %0, [%1], %2;"
                         : "=r"(old) : "r"(acnt_a), "r"(1u) : "memory");
            if (old == 8u * (unsigned)t + 7u)
                asm volatile("st.release.gpu.global.u32 [%0], %1;"
                             :: "l"(&g_tag[blockIdx.x]),
                                "r"(tagbase + (unsigned)(t + 1)) : "memory");
        }

        // stash h_t; flush 32 steps at once (off the release path)
        if (lane == (t & 31)) h_keep = hn;
        if ((t & 31) == 31) {
            int tb = t & ~31;
            outseq[(size_t)(tb + lane) * Dm + dim] = h_keep;
        }
        zx_cur = zx_next;
    }
}

// ---------------- kernel 4: emit final h -------------------------------------
__global__ void copy_out_kernel(float* __restrict__ out) {
    out[threadIdx.x] = g_seq[0][(size_t)(Tm - 1) * Dm + threadIdx.x];
}

// ---------------- launch ------------------------------------------------------
extern "C" void kernel_launch(void* const* d_in, const int* in_sizes, int n_in,
                              void* d_out, int out_size) {
    const float* x    = (const float*)d_in[0];
    const float* rn   = (const float*)d_in[1];
    const float* dtp  = (const float*)d_in[2];
    const float* rw   = (const float*)d_in[3];
    const float* rb   = (const float*)d_in[4];
    const float* Wf1  = (const float*)d_in[5];
    const float* bf1  = (const float*)d_in[6];
    const float* Wf2  = (const float*)d_in[7];
    const float* bf2  = (const float*)d_in[8];
    const float* Wta  = (const float*)d_in[9];
    const float* bta  = (const float*)d_in[10];
    const float* Wtb  = (const float*)d_in[11];
    const float* btb  = (const float*)d_in[12];

    // launch slots: 1=bias, 2=wt, 3=gemm0, 4=scan0, 5=gemm1, 6=scan1 (ncu -s5)
    bias_kernel<<<(Tm * Dm) / 256, 256>>>(x, rn, rw, rb);
    wt_kernel<<<dim3(32, 32, 16), dim3(32, 8)>>>(Wf1, Wf2, Wta, Wtb);

    for (int l = 0; l < Lm; ++l) {
        dim3 grid(4 * Dm / 64, Tm / 128);
        gemm_zx<<<grid, 256>>>(Wf1, Wf2, Wta, Wtb, bf1, bf2, bta, btb, l);
        scan_kernel<<<128, 256>>>(dtp, l);
    }

    copy_out_kernel<<<1, Dm>>>((float*)d_out);
}

// round 15
// speedup vs baseline: 2.2007x; 2.2007x over previous
#include <cuda_runtime.h>
#include <cuda_bf16.h>

#define Dm 1024
#define Tm 2048
#define Lm 4

typedef unsigned long long u64;

// ---------------- device scratch (allocation-free rule) ---------------------
__device__ __align__(16)  float g_seq[2][Tm * Dm];              // ping-pong seq
__device__ __align__(16)  float g_zx[(size_t)Tm * 4 * Dm];      // x-part + bias
__device__ __align__(16)  float g_wt[(size_t)Lm * 4 * Dm * Dm]; // Wh^T [l][gate][dim][k]
__device__ __align__(128) u64   g_ht[2][Dm];                    // {tag<<32 | h bits}, by parity

// ---------------- f32x2 helpers (sm_103a packed fp32) -----------------------
__device__ __forceinline__ u64 ffma2(u64 a, u64 b, u64 c) {
    u64 d;
    asm("fma.rn.f32x2 %0, %1, %2, %3;" : "=l"(d) : "l"(a), "l"(b), "l"(c));
    return d;
}
__device__ __forceinline__ u64 fadd2(u64 a, u64 b) {
    u64 d;
    asm("add.rn.f32x2 %0, %1, %2;" : "=l"(d) : "l"(a), "l"(b));
    return d;
}
__device__ __forceinline__ u64 pack2(float x, float y) {
    u64 r;
    asm("mov.b64 %0, {%1, %2};" : "=l"(r)
        : "r"(__float_as_uint(x)), "r"(__float_as_uint(y)));
    return r;
}
__device__ __forceinline__ float hsum2(u64 v) {
    unsigned lo, hi;
    asm("mov.b64 {%0, %1}, %2;" : "=r"(lo), "=r"(hi) : "l"(v));
    return __uint_as_float(lo) + __uint_as_float(hi);
}

// fast, saturation-safe tanh / sigmoid (MUFU-based)
__device__ __forceinline__ float fast_tanh(float x) {
    float e = __expf(-2.0f * fabsf(x));
    float r = __fdividef(1.0f - e, 1.0f + e);
    return copysignf(r, x);
}
__device__ __forceinline__ float fast_sigmoid(float u) {
    float e = __expf(-fabsf(u));
    float r = __fdividef(1.0f, 1.0f + e);
    return (u >= 0.0f) ? r : (1.0f - r);
}

// ---------------- kernel 1: Re bias-add + tag-word reset ---------------------
__global__ void bias_kernel(const float* __restrict__ x, const float* __restrict__ rn,
                            const float* __restrict__ w, const float* __restrict__ b) {
    int i = blockIdx.x * 256 + threadIdx.x;
    if (i < Dm) { g_ht[0][i] = 0ull; g_ht[1][i] = 0ull; }   // kill stale tags
    int j = i & (Dm - 1);
    g_seq[0][i] = x[i] + rn[0] * w[j] + b[j];
}

// ---------------- kernel 1b: transpose Wh -> g_wt[l][gate][dim][k] ----------
__global__ void wt_kernel(const float* __restrict__ Wf1, const float* __restrict__ Wf2,
                          const float* __restrict__ Wta, const float* __restrict__ Wtb) {
    __shared__ float tile[32][33];
    const int lg = blockIdx.z;              // l*4 + gate
    const int l = lg >> 2, gate = lg & 3;
    const float* Wg = (gate == 0) ? Wf1 : ((gate == 1) ? Wf2 : ((gate == 2) ? Wta : Wtb));
    const float* W = Wg + (size_t)l * 2 * Dm * Dm;
    const int k0 = blockIdx.x * 32, d0 = blockIdx.y * 32;
    const int tx = threadIdx.x, ty = threadIdx.y;
#pragma unroll
    for (int r = ty; r < 32; r += 8)
        tile[r][tx] = W[(size_t)(Dm + k0 + r) * Dm + d0 + tx];   // h-part rows
    __syncthreads();
#pragma unroll
    for (int r = ty; r < 32; r += 8)
        g_wt[((size_t)lg * Dm + d0 + r) * Dm + k0 + tx] = tile[tx][r];
}

// ---------------- kernel 2: Zx = seq_in @ Wx + bias (f32x2 GEMM) -------------
__global__ __launch_bounds__(256, 2) void gemm_zx(
    const float* __restrict__ Wf1, const float* __restrict__ Wf2,
    const float* __restrict__ Wta, const float* __restrict__ Wtb,
    const float* __restrict__ bf1, const float* __restrict__ bf2,
    const float* __restrict__ bta, const float* __restrict__ btb,
    int layer)
{
    __shared__ u64   As2[8][128];
    __shared__ float Bsf[8][64][2];

    const int tid = threadIdx.x;
    const int tx = tid & 15;
    const int ty = tid >> 4;
    const int m0 = blockIdx.y * 128;
    const int n0 = blockIdx.x * 64;
    const int blk = n0 >> 10;
    const int j0  = n0 & (Dm - 1);

    const float* Wb = (blk == 0) ? Wf1 : ((blk == 1) ? Wf2 : ((blk == 2) ? Wta : Wtb));
    const float* bb = (blk == 0) ? bf1 : ((blk == 1) ? bf2 : ((blk == 2) ? bta : btb));
    const float* Bp = Wb + (size_t)layer * 2 * Dm * Dm + j0;
    const float* A  = g_seq[layer & 1];

    u64 acc[8][4];
#pragma unroll
    for (int i = 0; i < 8; i++)
#pragma unroll
        for (int j = 0; j < 4; j++) acc[i][j] = 0ull;

    for (int k0 = 0; k0 < Dm; k0 += 16) {
#pragma unroll
        for (int it = 0; it < 2; it++) {
            int i   = tid + it * 256;
            int row = i >> 2;
            int f4  = i & 3;
            float4 v = *(const float4*)(A + (size_t)(m0 + row) * Dm + k0 + f4 * 4);
            As2[f4 * 2 + 0][row] = pack2(v.x, v.y);
            As2[f4 * 2 + 1][row] = pack2(v.z, v.w);
        }
        {
            int kr = tid >> 4;
            int j4 = tid & 15;
            float4 v = *(const float4*)(Bp + (size_t)(k0 + kr) * Dm + j4 * 4);
            Bsf[kr >> 1][j4 * 4 + 0][kr & 1] = v.x;
            Bsf[kr >> 1][j4 * 4 + 1][kr & 1] = v.y;
            Bsf[kr >> 1][j4 * 4 + 2][kr & 1] = v.z;
            Bsf[kr >> 1][j4 * 4 + 3][kr & 1] = v.w;
        }
        __syncthreads();
#pragma unroll
        for (int kk = 0; kk < 8; kk++) {
            u64 a2[8], b2[4];
#pragma unroll
            for (int ii = 0; ii < 8; ii++) a2[ii] = As2[kk][ii * 16 + ty];
#pragma unroll
            for (int jj = 0; jj < 4; jj++) b2[jj] = *(const u64*)&Bsf[kk][jj * 16 + tx][0];
#pragma unroll
            for (int ii = 0; ii < 8; ii++)
#pragma unroll
                for (int jj = 0; jj < 4; jj++)
                    acc[ii][jj] = ffma2(a2[ii], b2[jj], acc[ii][jj]);
        }
        __syncthreads();
    }

    float bias[4];
#pragma unroll
    for (int jj = 0; jj < 4; jj++) bias[jj] = bb[(size_t)layer * Dm + j0 + jj * 16 + tx];
#pragma unroll
    for (int ii = 0; ii < 8; ii++) {
        size_t row = (size_t)(m0 + ii * 16 + ty);
#pragma unroll
        for (int jj = 0; jj < 4; jj++)
            g_zx[row * 4096 + n0 + jj * 16 + tx] = hsum2(acc[ii][jj]) + bias[jj];
    }
}

// ---------------- kernel 3: sequential scan (tagged-h, 4 polling warps) ------
// 128 CTAs x 256 threads. CTA b owns dims 8b..8b+7, warp w -> dim.
// Lane = blk*8 + chunk (gate, 128-wide k range). h_t lives in g_ht[t&1] as
// {tag|bits}. Warps 0-3 poll (lane p owns 8 words = 64B); on detect the data
// is already in registers -> STS -> one BAR. Producers: lane0 st.relaxed one
// 8B word (tag travels with value; no fence/counter/RED).
__global__ __launch_bounds__(256, 1) void scan_kernel(const float* __restrict__ dt_ptr,
                                                      int layer)
{
    __shared__ __align__(16) float sh[2][Dm];   // double-buffered h stage

    const int tid  = threadIdx.x;
    const int lane = tid & 31;
    const int w    = tid >> 5;
    const int blk  = lane >> 3;
    const int ch   = lane & 7;
    const int dim  = blockIdx.x * 8 + w;
    const float dt = dt_ptr[0];
    const unsigned tagbase = (unsigned)layer * (unsigned)Tm;

    // coalesced weight load from transposed scratch: [l][gate][dim][k]
    const float* Wtp = g_wt + ((size_t)(layer * 4 + blk) * Dm + dim) * Dm + ch * 128;
    u64 wreg[64];
#pragma unroll
    for (int i = 0; i < 32; i++) {
        float4 v = *(const float4*)(Wtp + 4 * i);
        wreg[2 * i + 0] = pack2(v.x, v.y);
        wreg[2 * i + 1] = pack2(v.z, v.w);
    }

    float* __restrict__ outseq = g_seq[(layer + 1) & 1];
    const bool zlane = (ch == 0);
    float zx_cur = zlane ? __ldg(&g_zx[(size_t)blk * Dm + dim]) : 0.0f;
    float h_keep = 0.0f;   // outseq stash: step (t & ~31) + lane

    // poll mapping (tid < 128): lane p owns h[d0 .. d0+7],
    // d0 = (p&7)*128 + (p>>3)*8  ->  c = p&7, f0 = 2*(p>>3)
    // STS targets sh[f0*32 + c*4 ..] and sh[(f0+1)*32 + c*4 ..] (conflict-free)
    const int pc = tid & 7;
    const int pf = tid >> 3;                  // 0..15 for tid<128
    const int poff  = pc * 128 + pf * 8;      // word offset into g_ht[par]
    const int soff  = (2 * pf) * 32 + pc * 4; // word offset into sh[par]

    for (int t = 0; t < Tm; ++t) {
        // ---- acquire + stage h_t (warps 0-3 only) ----
        if (tid < 128) {
            float* sp = &sh[t & 1][soff];
            if (t == 0) {
                *(float4*)sp        = make_float4(0.f, 0.f, 0.f, 0.f);
                *(float4*)(sp + 32) = make_float4(0.f, 0.f, 0.f, 0.f);
            } else {
                const u64* pp = &g_ht[t & 1][poff];
                const unsigned target = tagbase + (unsigned)t;
                u64 v0, v1, v2, v3, v4, v5, v6, v7;
                for (;;) {
                    asm volatile("ld.volatile.global.v2.u64 {%0,%1}, [%2];"
                                 : "=l"(v0), "=l"(v1) : "l"(pp + 0) : "memory");
                    asm volatile("ld.volatile.global.v2.u64 {%0,%1}, [%2];"
                                 : "=l"(v2), "=l"(v3) : "l"(pp + 2) : "memory");
                    asm volatile("ld.volatile.global.v2.u64 {%0,%1}, [%2];"
                                 : "=l"(v4), "=l"(v5) : "l"(pp + 4) : "memory");
                    asm volatile("ld.volatile.global.v2.u64 {%0,%1}, [%2];"
                                 : "=l"(v6), "=l"(v7) : "l"(pp + 6) : "memory");
                    bool ok = ((unsigned)(v0 >> 32) == target) &
                              ((unsigned)(v1 >> 32) == target) &
                              ((unsigned)(v2 >> 32) == target) &
                              ((unsigned)(v3 >> 32) == target) &
                              ((unsigned)(v4 >> 32) == target) &
                              ((unsigned)(v5 >> 32) == target) &
                              ((unsigned)(v6 >> 32) == target) &
                              ((unsigned)(v7 >> 32) == target);
                    if (__all_sync(0xffffffffu, ok)) break;
                }
                float4 a, b;
                a.x = __uint_as_float((unsigned)v0);
                a.y = __uint_as_float((unsigned)v1);
                a.z = __uint_as_float((unsigned)v2);
                a.w = __uint_as_float((unsigned)v3);
                b.x = __uint_as_float((unsigned)v4);
                b.y = __uint_as_float((unsigned)v5);
                b.z = __uint_as_float((unsigned)v6);
                b.w = __uint_as_float((unsigned)v7);
                *(float4*)sp        = a;
                *(float4*)(sp + 32) = b;
            }
        }
        __syncthreads();   // single BAR per step: sh[t&1] ready for all warps

        // zx prefetch for t+1 (independent; hides under compute)
        float zx_next = (zlane && t + 1 < Tm)
            ? __ldg(&g_zx[(size_t)(t + 1) * 4096 + blk * Dm + dim]) : 0.0f;

        // ---- partial dot: 128 k via 64 packed FMAs ----
        u64 a0 = 0ull, a1 = 0ull, a2 = 0ull, a3 = 0ull;
        const float4* sh4 = (const float4*)sh[t & 1];
#pragma unroll
        for (int f = 0; f < 32; f += 2) {
            float4 h0 = sh4[f * 8 + ch];
            float4 h1 = sh4[(f + 1) * 8 + ch];
            a0 = ffma2(pack2(h0.x, h0.y), wreg[2 * f + 0], a0);
            a1 = ffma2(pack2(h0.z, h0.w), wreg[2 * f + 1], a1);
            a2 = ffma2(pack2(h1.x, h1.y), wreg[2 * f + 2], a2);
            a3 = ffma2(pack2(h1.z, h1.w), wreg[2 * f + 3], a3);
        }
        float s = hsum2(fadd2(fadd2(a0, a1), fadd2(a2, a3)));
        s += __shfl_xor_sync(0xffffffffu, s, 1);
        s += __shfl_xor_sync(0xffffffffu, s, 2);
        s += __shfl_xor_sync(0xffffffffu, s, 4);
        if (zlane) s += zx_cur;

        float z1 = __shfl_sync(0xffffffffu, s, 0);
        float z2 = __shfl_sync(0xffffffffu, s, 8);
        float za = __shfl_sync(0xffffffffu, s, 16);
        float zb = __shfl_sync(0xffffffffu, s, 24);

        float f1 = fast_tanh(z1);
        float f2 = fast_tanh(z2);
        float g  = fast_sigmoid(zb - za * dt);   // sigmoid(-za*dt+zb)
        float hn = g * f1 + (1.0f - g) * f2;

        // ---- publish h(t+1): ONE relaxed 8B store (tag rides with bits) ----
        if (lane == 0 && t + 1 < Tm) {
            u64 pk = ((u64)(tagbase + (unsigned)(t + 1)) << 32)
                   | (u64)__float_as_uint(hn);
            asm volatile("st.relaxed.gpu.global.b64 [%0], %1;"
                         :: "l"(&g_ht[(t + 1) & 1][dim]), "l"(pk) : "memory");
        }

        // stash h_t; flush 32 steps at once (off the publish path)
        if (lane == (t & 31)) h_keep = hn;
        if ((t & 31) == 31) {
            int tb = t & ~31;
            outseq[(size_t)(tb + lane) * Dm + dim] = h_keep;
        }
        zx_cur = zx_next;
        // no trailing sync: sh double-buffer + per-step BAR bounds skew;
        // g_ht lap-overwrite needs tag t+2 in this parity, which requires all
        // CTAs to have consumed step t (published t+1) -> safe.
    }
}

// ---------------- kernel 4: emit final h -------------------------------------
__global__ void copy_out_kernel(float* __restrict__ out) {
    out[threadIdx.x] = g_seq[0][(size_t)(Tm - 1) * Dm + threadIdx.x];
}

// ---------------- launch ------------------------------------------------------
extern "C" void kernel_launch(void* const* d_in, const int* in_sizes, int n_in,
                              void* d_out, int out_size) {
    const float* x    = (const float*)d_in[0];
    const float* rn   = (const float*)d_in[1];
    const float* dtp  = (const float*)d_in[2];
    const float* rw   = (const float*)d_in[3];
    const float* rb   = (const float*)d_in[4];
    const float* Wf1  = (const float*)d_in[5];
    const float* bf1  = (const float*)d_in[6];
    const float* Wf2  = (const float*)d_in[7];
    const float* bf2  = (const float*)d_in[8];
    const float* Wta  = (const float*)d_in[9];
    const float* bta  = (const float*)d_in[10];
    const float* Wtb  = (const float*)d_in[11];
    const float* btb  = (const float*)d_in[12];

    // launch slots: 1=bias, 2=wt, 3=gemm0, 4=scan0, 5=gemm1, 6=scan1 (ncu -s5)
    bias_kernel<<<(Tm * Dm) / 256, 256>>>(x, rn, rw, rb);
    wt_kernel<<<dim3(32, 32, 16), dim3(32, 8)>>>(Wf1, Wf2, Wta, Wtb);

    for (int l = 0; l < Lm; ++l) {
        dim3 grid(4 * Dm / 64, Tm / 128);
        gemm_zx<<<grid, 256>>>(Wf1, Wf2, Wta, Wtb, bf1, bf2, bta, btb, l);
        scan_kernel<<<128, 256>>>(dtp, l);
    }

    copy_out_kernel<<<1, Dm>>>((float*)d_out);
}

// round 16
// speedup vs baseline: 3.0899x; 1.4041x over previous
#include <cuda_runtime.h>
#include <cuda_bf16.h>

#define Dm 1024
#define Tm 2048
#define Lm 4

typedef unsigned long long u64;

// ---------------- device scratch (allocation-free rule) ---------------------
__device__ __align__(16)  float g_seq[2][Tm * Dm];              // ping-pong seq
__device__ __align__(16)  float g_zx[(size_t)Tm * 4 * Dm];      // x-part + bias
__device__ __align__(16)  float g_wt[(size_t)Lm * 4 * Dm * Dm]; // Wh^T [l][gate][dim][k]
__device__ __align__(128) u64   g_ht[2][Dm];                    // {tag<<32 | h bits}
__device__ unsigned g_bar_count;                                // monotonic / launch

// ---------------- f32x2 helpers (sm_103a packed fp32) -----------------------
__device__ __forceinline__ u64 ffma2(u64 a, u64 b, u64 c) {
    u64 d;
    asm("fma.rn.f32x2 %0, %1, %2, %3;" : "=l"(d) : "l"(a), "l"(b), "l"(c));
    return d;
}
__device__ __forceinline__ u64 fadd2(u64 a, u64 b) {
    u64 d;
    asm("add.rn.f32x2 %0, %1, %2;" : "=l"(d) : "l"(a), "l"(b));
    return d;
}
__device__ __forceinline__ u64 pack2(float x, float y) {
    u64 r;
    asm("mov.b64 %0, {%1, %2};" : "=l"(r)
        : "r"(__float_as_uint(x)), "r"(__float_as_uint(y)));
    return r;
}
__device__ __forceinline__ float hsum2(u64 v) {
    unsigned lo, hi;
    asm("mov.b64 {%0, %1}, %2;" : "=r"(lo), "=r"(hi) : "l"(v));
    return __uint_as_float(lo) + __uint_as_float(hi);
}

// fast, saturation-safe tanh / sigmoid (MUFU-based)
__device__ __forceinline__ float fast_tanh(float x) {
    float e = __expf(-2.0f * fabsf(x));
    float r = __fdividef(1.0f - e, 1.0f + e);
    return copysignf(r, x);
}
__device__ __forceinline__ float fast_sigmoid(float u) {
    float e = __expf(-fabsf(u));
    float r = __fdividef(1.0f, 1.0f + e);
    return (u >= 0.0f) ? r : (1.0f - r);
}

// ---------------- kernel 1: Re bias-add + barrier/tag reset ------------------
__global__ void bias_kernel(const float* __restrict__ x, const float* __restrict__ rn,
                            const float* __restrict__ w, const float* __restrict__ b) {
    if (blockIdx.x == 0 && threadIdx.x == 0) g_bar_count = 0u;
    int i = blockIdx.x * 256 + threadIdx.x;
    if (i < Dm) { g_ht[0][i] = 0ull; g_ht[1][i] = 0ull; }   // kill stale tags
    int j = i & (Dm - 1);
    g_seq[0][i] = x[i] + rn[0] * w[j] + b[j];
}

// ---------------- kernel 1b: transpose Wh -> g_wt[l][gate][dim][k] ----------
__global__ void wt_kernel(const float* __restrict__ Wf1, const float* __restrict__ Wf2,
                          const float* __restrict__ Wta, const float* __restrict__ Wtb) {
    __shared__ float tile[32][33];
    const int lg = blockIdx.z;              // l*4 + gate
    const int l = lg >> 2, gate = lg & 3;
    const float* Wg = (gate == 0) ? Wf1 : ((gate == 1) ? Wf2 : ((gate == 2) ? Wta : Wtb));
    const float* W = Wg + (size_t)l * 2 * Dm * Dm;
    const int k0 = blockIdx.x * 32, d0 = blockIdx.y * 32;
    const int tx = threadIdx.x, ty = threadIdx.y;
#pragma unroll
    for (int r = ty; r < 32; r += 8)
        tile[r][tx] = W[(size_t)(Dm + k0 + r) * Dm + d0 + tx];   // h-part rows
    __syncthreads();
#pragma unroll
    for (int r = ty; r < 32; r += 8)
        g_wt[((size_t)lg * Dm + d0 + r) * Dm + k0 + tx] = tile[tx][r];
}

// ---------------- kernel 2: Zx = seq_in @ Wx + bias (f32x2 GEMM) -------------
__global__ __launch_bounds__(256, 2) void gemm_zx(
    const float* __restrict__ Wf1, const float* __restrict__ Wf2,
    const float* __restrict__ Wta, const float* __restrict__ Wtb,
    const float* __restrict__ bf1, const float* __restrict__ bf2,
    const float* __restrict__ bta, const float* __restrict__ btb,
    int layer)
{
    __shared__ u64   As2[8][128];
    __shared__ float Bsf[8][64][2];

    const int tid = threadIdx.x;
    const int tx = tid & 15;
    const int ty = tid >> 4;
    const int m0 = blockIdx.y * 128;
    const int n0 = blockIdx.x * 64;
    const int blk = n0 >> 10;
    const int j0  = n0 & (Dm - 1);

    const float* Wb = (blk == 0) ? Wf1 : ((blk == 1) ? Wf2 : ((blk == 2) ? Wta : Wtb));
    const float* bb = (blk == 0) ? bf1 : ((blk == 1) ? bf2 : ((blk == 2) ? bta : btb));
    const float* Bp = Wb + (size_t)layer * 2 * Dm * Dm + j0;
    const float* A  = g_seq[layer & 1];

    u64 acc[8][4];
#pragma unroll
    for (int i = 0; i < 8; i++)
#pragma unroll
        for (int j = 0; j < 4; j++) acc[i][j] = 0ull;

    for (int k0 = 0; k0 < Dm; k0 += 16) {
#pragma unroll
        for (int it = 0; it < 2; it++) {
            int i   = tid + it * 256;
            int row = i >> 2;
            int f4  = i & 3;
            float4 v = *(const float4*)(A + (size_t)(m0 + row) * Dm + k0 + f4 * 4);
            As2[f4 * 2 + 0][row] = pack2(v.x, v.y);
            As2[f4 * 2 + 1][row] = pack2(v.z, v.w);
        }
        {
            int kr = tid >> 4;
            int j4 = tid & 15;
            float4 v = *(const float4*)(Bp + (size_t)(k0 + kr) * Dm + j4 * 4);
            Bsf[kr >> 1][j4 * 4 + 0][kr & 1] = v.x;
            Bsf[kr >> 1][j4 * 4 + 1][kr & 1] = v.y;
            Bsf[kr >> 1][j4 * 4 + 2][kr & 1] = v.z;
            Bsf[kr >> 1][j4 * 4 + 3][kr & 1] = v.w;
        }
        __syncthreads();
#pragma unroll
        for (int kk = 0; kk < 8; kk++) {
            u64 a2[8], b2[4];
#pragma unroll
            for (int ii = 0; ii < 8; ii++) a2[ii] = As2[kk][ii * 16 + ty];
#pragma unroll
            for (int jj = 0; jj < 4; jj++) b2[jj] = *(const u64*)&Bsf[kk][jj * 16 + tx][0];
#pragma unroll
            for (int ii = 0; ii < 8; ii++)
#pragma unroll
                for (int jj = 0; jj < 4; jj++)
                    acc[ii][jj] = ffma2(a2[ii], b2[jj], acc[ii][jj]);
        }
        __syncthreads();
    }

    float bias[4];
#pragma unroll
    for (int jj = 0; jj < 4; jj++) bias[jj] = bb[(size_t)layer * Dm + j0 + jj * 16 + tx];
#pragma unroll
    for (int ii = 0; ii < 8; ii++) {
        size_t row = (size_t)(m0 + ii * 16 + ty);
#pragma unroll
        for (int jj = 0; jj < 4; jj++)
            g_zx[row * 4096 + n0 + jj * 16 + tx] = hsum2(acc[ii][jj]) + bias[jj];
    }
}

// ---------------- kernel 3: sequential scan (R9 barrier + tagged-h verify) ---
// 128 CTAs x 256 threads. CTA b owns dims 8b..8b+7, warp w -> dim.
// Lane = blk*8 + chunk: blk picks gate, ch picks 128-wide k range.
// Publish: lane0 st.relaxed ONE tagged 8B word {tag|h}. Arrival: tid0
// red.RELAXED on the counter (no fence: tags make staging self-verifying).
// Detect: warp0 polls ONE counter word (minimal L2 traffic — the measured
// constraint). Stage: 2x v2.u64 loads + tag check, retry on stale (rare).
__global__ __launch_bounds__(256, 1) void scan_kernel(const float* __restrict__ dt_ptr,
                                                      int layer)
{
    __shared__ __align__(16) float sh[2][Dm];   // double-buffered h stage

    const int tid  = threadIdx.x;
    const int lane = tid & 31;
    const int w    = tid >> 5;
    const int blk  = lane >> 3;
    const int ch   = lane & 7;
    const int dim  = blockIdx.x * 8 + w;
    const float dt = dt_ptr[0];
    const unsigned tagb = (unsigned)layer * (unsigned)Tm;   // tags this layer
    const unsigned cntb = (unsigned)layer * 2047u * 128u;   // counter base
    unsigned* const cnt = &g_bar_count;

    // coalesced weight load from transposed scratch: [l][gate][dim][k]
    const float* Wtp = g_wt + ((size_t)(layer * 4 + blk) * Dm + dim) * Dm + ch * 128;
    u64 wreg[64];
#pragma unroll
    for (int i = 0; i < 32; i++) {
        float4 v = *(const float4*)(Wtp + 4 * i);
        wreg[2 * i + 0] = pack2(v.x, v.y);
        wreg[2 * i + 1] = pack2(v.z, v.w);
    }

    float* __restrict__ outseq = g_seq[(layer + 1) & 1];
    const bool zlane = (ch == 0);
    float zx_cur = zlane ? __ldg(&g_zx[(size_t)blk * Dm + dim]) : 0.0f;

    // staging indices: thread handles h[sc*128 + sf*4 .. +3]
    const int sc = tid & 7, sf = tid >> 3;
    const int htoff = sc * 128 + sf * 4;
    float* const mysh0 = &sh[0][sf * 32 + sc * 4];
    float* const mysh1 = &sh[1][sf * 32 + sc * 4];

    for (int t = 0; t < Tm; ++t) {
        // ---- stage h_t (tag-verified; counter already guarantees near-ready)
        float* mysh = (t & 1) ? mysh1 : mysh0;
        if (t == 0) {
            mysh[0] = 0.0f; mysh[1] = 0.0f; mysh[2] = 0.0f; mysh[3] = 0.0f;
        } else {
            const u64* pp = &g_ht[t & 1][htoff];
            const unsigned target = tagb + (unsigned)t;
            u64 v0, v1, v2, v3;
            for (;;) {
                asm volatile("ld.volatile.global.v2.u64 {%0,%1}, [%2];"
                             : "=l"(v0), "=l"(v1) : "l"(pp + 0) : "memory");
                asm volatile("ld.volatile.global.v2.u64 {%0,%1}, [%2];"
                             : "=l"(v2), "=l"(v3) : "l"(pp + 2) : "memory");
                if (((unsigned)(v0 >> 32) == target) &
                    ((unsigned)(v1 >> 32) == target) &
                    ((unsigned)(v2 >> 32) == target) &
                    ((unsigned)(v3 >> 32) == target)) break;   // usually 1st try
            }
            mysh[0] = __uint_as_float((unsigned)v0);
            mysh[1] = __uint_as_float((unsigned)v1);
            mysh[2] = __uint_as_float((unsigned)v2);
            mysh[3] = __uint_as_float((unsigned)v3);
        }
        __syncthreads();

        // zx prefetch for t+1 (overlaps compute)
        float zx_next = (zlane && t + 1 < Tm)
            ? __ldg(&g_zx[(size_t)(t + 1) * 4096 + blk * Dm + dim]) : 0.0f;

        // ---- partial dot: 128 k via 64 packed FMAs, 4 accumulator chains ----
        u64 a0 = 0ull, a1 = 0ull, a2 = 0ull, a3 = 0ull;
        const float4* sh4 = (const float4*)sh[t & 1];
#pragma unroll
        for (int f = 0; f < 32; f += 2) {
            float4 h0 = sh4[f * 8 + ch];
            float4 h1 = sh4[(f + 1) * 8 + ch];
            a0 = ffma2(pack2(h0.x, h0.y), wreg[2 * f + 0], a0);
            a1 = ffma2(pack2(h0.z, h0.w), wreg[2 * f + 1], a1);
            a2 = ffma2(pack2(h1.x, h1.y), wreg[2 * f + 2], a2);
            a3 = ffma2(pack2(h1.z, h1.w), wreg[2 * f + 3], a3);
        }
        float s = hsum2(fadd2(fadd2(a0, a1), fadd2(a2, a3)));
        s += __shfl_xor_sync(0xffffffffu, s, 1);
        s += __shfl_xor_sync(0xffffffffu, s, 2);
        s += __shfl_xor_sync(0xffffffffu, s, 4);
        if (zlane) s += zx_cur;

        float z1 = __shfl_sync(0xffffffffu, s, 0);
        float z2 = __shfl_sync(0xffffffffu, s, 8);
        float za = __shfl_sync(0xffffffffu, s, 16);
        float zb = __shfl_sync(0xffffffffu, s, 24);

        float f1 = fast_tanh(z1);
        float f2 = fast_tanh(z2);
        float g  = fast_sigmoid(zb - za * dt);   // sigmoid(-za*dt+zb)
        float hn = g * f1 + (1.0f - g) * f2;

        if (lane == 0) {
            if (t + 1 < Tm) {
                // ONE relaxed 8B store: tag travels with the value
                u64 pk = ((u64)(tagb + (unsigned)(t + 1)) << 32)
                       | (u64)__float_as_uint(hn);
                asm volatile("st.relaxed.gpu.global.b64 [%0], %1;"
                             :: "l"(&g_ht[(t + 1) & 1][dim]), "l"(pk) : "memory");
            }
            outseq[(size_t)t * Dm + dim] = hn;   // no fence anywhere drains this
        }

        if (t + 1 < Tm) {
            __syncthreads();                     // all publishes issued
            if (tid == 0)                        // RELAXED arrival: no drain
                asm volatile("red.relaxed.gpu.global.add.u32 [%0], %1;"
                             :: "l"(cnt), "r"(1u) : "memory");
            if (w == 0) {                        // warp0 polls ONE word
                const unsigned target = cntb + 128u * (unsigned)(t + 1);
                unsigned v;
                do {
                    asm volatile("ld.relaxed.gpu.global.u32 %0, [%1];"
                                 : "=r"(v) : "l"(cnt) : "memory");
                } while ((int)(v - target) < 0);
            }
            __syncthreads();                     // release the CTA
        }
        zx_cur = zx_next;
    }
}

// ---------------- kernel 4: emit final h -------------------------------------
__global__ void copy_out_kernel(float* __restrict__ out) {
    out[threadIdx.x] = g_seq[0][(size_t)(Tm - 1) * Dm + threadIdx.x];
}

// ---------------- launch ------------------------------------------------------
extern "C" void kernel_launch(void* const* d_in, const int* in_sizes, int n_in,
                              void* d_out, int out_size) {
    const float* x    = (const float*)d_in[0];
    const float* rn   = (const float*)d_in[1];
    const float* dtp  = (const float*)d_in[2];
    const float* rw   = (const float*)d_in[3];
    const float* rb   = (const float*)d_in[4];
    const float* Wf1  = (const float*)d_in[5];
    const float* bf1  = (const float*)d_in[6];
    const float* Wf2  = (const float*)d_in[7];
    const float* bf2  = (const float*)d_in[8];
    const float* Wta  = (const float*)d_in[9];
    const float* bta  = (const float*)d_in[10];
    const float* Wtb  = (const float*)d_in[11];
    const float* btb  = (const float*)d_in[12];

    // launch slots: 1=bias, 2=wt, 3=gemm0, 4=scan0, 5=gemm1, 6=scan1 (ncu -s5)
    bias_kernel<<<(Tm * Dm) / 256, 256>>>(x, rn, rw, rb);
    wt_kernel<<<dim3(32, 32, 16), dim3(32, 8)>>>(Wf1, Wf2, Wta, Wtb);

    for (int l = 0; l < Lm; ++l) {
        dim3 grid(4 * Dm / 64, Tm / 128);
        gemm_zx<<<grid, 256>>>(Wf1, Wf2, Wta, Wtb, bf1, bf2, bta, btb, l);
        scan_kernel<<<128, 256>>>(dtp, l);
    }

    copy_out_kernel<<<1, Dm>>>((float*)d_out);
}